// round 2
// baseline (speedup 1.0000x reference)
#include <cuda_runtime.h>
#include <cstdint>

#define T_STEPS 256
#define B_SZ 8
#define N_ST 128
#define E_DIM 512
#define D_DIM 80
#define M_DIM 512
#define P_DIM 256
#define NEG (-1.0e10f)
#define HALF_LOG2PI 0.9189385332046727f

// ---------------- global scratch (no allocations allowed) ----------------
__device__ float g_gih[2048 * 2048];   // (t*8+b, 2048) : pre1@W_ih.T + b_ih + b_hh
__device__ float g_base[1024 * 256];   // (b*128+n, 256): inputs@ow0[:, :512].T + ob0
__device__ float g_hall[2048 * 512];   // (t*8+b, 512)  : h_t
__device__ float g_hpart[2048 * 256];  // (t*8+b, 256)  : h@ow0[:, 512:].T
__device__ float g_hbuf[8192];         // double-buffered h state (2 x 8 x 512)
__device__ float g_em[2048 * 128];     // (t*8+b, n)
__device__ float g_tv[2048 * 128];     // (t*8+b, n)
__device__ unsigned g_cnt = 0;
__device__ unsigned g_gen = 0;

__device__ __forceinline__ float sigm(float x) { return 1.f / (1.f + expf(-x)); }

__device__ __forceinline__ void gbar(unsigned ncta) {
    __syncthreads();
    __threadfence();
    if (threadIdx.x == 0) {
        unsigned gen = *((volatile unsigned*)&g_gen);
        if (atomicAdd(&g_cnt, 1u) == ncta - 1u) {
            atomicExch(&g_cnt, 0u);
            __threadfence();
            *((volatile unsigned*)&g_gen) = gen + 1u;
        } else {
            while (*((volatile unsigned*)&g_gen) == gen) {}
        }
    }
    __syncthreads();
}

// ---------------- K_A: prenet (all t) + gates-input precompute ----------------
// rows r = t*8+b (2048), 16 rows per CTA, grid 128
__global__ __launch_bounds__(256) void k_prenet(
    const float* __restrict__ mels, const float* __restrict__ w0,
    const float* __restrict__ w1, const float* __restrict__ wih,
    const float* __restrict__ bih, const float* __restrict__ bhh) {
    __shared__ __align__(16) float in_s[16 * 80];
    __shared__ __align__(16) float p0[16 * 256];
    __shared__ __align__(16) float p1[16 * 256];
    int tid = threadIdx.x;
    int r0 = blockIdx.x * 16;

    for (int e = tid; e < 16 * 80; e += 256) {
        int i = e / 80, d = e - i * 80;
        int r = r0 + i, t = r >> 3, b = r & 7;
        in_s[e] = (t == 0) ? 0.f : mels[(b * 80 + d) * 256 + (t - 1)];
    }
    __syncthreads();
    {   // pre0 = relu(ar_x @ w0.T)   K=80
        int c = tid;
        float acc[16];
#pragma unroll
        for (int i = 0; i < 16; ++i) acc[i] = 0.f;
        const float* wr = w0 + c * 80;
        for (int k = 0; k < 80; k += 2) {
            float wa = wr[k], wb = wr[k + 1];
#pragma unroll
            for (int i = 0; i < 16; ++i) {
                acc[i] = fmaf(in_s[i * 80 + k], wa, acc[i]);
                acc[i] = fmaf(in_s[i * 80 + k + 1], wb, acc[i]);
            }
        }
#pragma unroll
        for (int i = 0; i < 16; ++i) p0[i * 256 + c] = fmaxf(acc[i], 0.f);
    }
    __syncthreads();
    {   // pre1 = relu(pre0 @ w1.T)   K=256
        int c = tid;
        float acc[16];
#pragma unroll
        for (int i = 0; i < 16; ++i) acc[i] = 0.f;
        const float2* wr = (const float2*)(w1 + c * 256);
#pragma unroll 2
        for (int k2 = 0; k2 < 128; ++k2) {
            float2 wv = wr[k2];
#pragma unroll
            for (int i = 0; i < 16; ++i) {
                float2 av = *(const float2*)&p0[i * 256 + 2 * k2];
                acc[i] = fmaf(av.x, wv.x, acc[i]);
                acc[i] = fmaf(av.y, wv.y, acc[i]);
            }
        }
#pragma unroll
        for (int i = 0; i < 16; ++i) p1[i * 256 + c] = fmaxf(acc[i], 0.f);
    }
    __syncthreads();
    // gih = pre1 @ wih.T + b_ih + b_hh   (2048 cols, 8 col-blocks)
    for (int cb = 0; cb < 8; ++cb) {
        int col = cb * 256 + tid;
        float acc[16];
#pragma unroll
        for (int i = 0; i < 16; ++i) acc[i] = 0.f;
        const float2* wr = (const float2*)(wih + (size_t)col * 256);
#pragma unroll 2
        for (int k2 = 0; k2 < 128; ++k2) {
            float2 wv = wr[k2];
#pragma unroll
            for (int i = 0; i < 16; ++i) {
                float2 av = *(const float2*)&p1[i * 256 + 2 * k2];
                acc[i] = fmaf(av.x, wv.x, acc[i]);
                acc[i] = fmaf(av.y, wv.y, acc[i]);
            }
        }
        float bias = bih[col] + bhh[col];
#pragma unroll
        for (int i = 0; i < 16; ++i)
            g_gih[(size_t)(r0 + i) * 2048 + col] = acc[i] + bias;
    }
}

// ---------------- K_base: base = inputs @ ow0[:, :512].T + ob0 ----------------
// rows 1024, 16/CTA, grid 64
__global__ __launch_bounds__(256) void k_base(
    const float* __restrict__ inputs, const float* __restrict__ ow0,
    const float* __restrict__ ob0) {
    __shared__ __align__(16) float a_s[16 * 512];
    int tid = threadIdx.x;
    int r0 = blockIdx.x * 16;
    const float* src = inputs + (size_t)r0 * 512;
    for (int e = tid; e < 8192; e += 256) a_s[e] = src[e];
    __syncthreads();
    int c = tid;
    float acc[16];
#pragma unroll
    for (int i = 0; i < 16; ++i) acc[i] = 0.f;
    const float2* wr = (const float2*)(ow0 + (size_t)c * 1024);
#pragma unroll 2
    for (int k2 = 0; k2 < 256; ++k2) {
        float2 wv = wr[k2];
#pragma unroll
        for (int i = 0; i < 16; ++i) {
            float2 av = *(const float2*)&a_s[i * 512 + 2 * k2];
            acc[i] = fmaf(av.x, wv.x, acc[i]);
            acc[i] = fmaf(av.y, wv.y, acc[i]);
        }
    }
    float bias = ob0[c];
#pragma unroll
    for (int i = 0; i < 16; ++i)
        g_base[(size_t)(r0 + i) * 256 + c] = acc[i] + bias;
}

// ---------------- K_scan: sequential LSTM over T with grid barrier ----------------
// grid MUST be 32 CTAs x 256 thr (8192 threads = 512 units x 16 k-slices)
__global__ __launch_bounds__(256) void k_scan(const float* __restrict__ whh) {
    __shared__ float h_s[4096];
    int tid = threadIdx.x;
    int gt = blockIdx.x * 256 + tid;
    int m = gt >> 4, s = gt & 15;

    if (gt < 8192) g_hbuf[gt] = 0.f;   // zero both h buffers
    float creg[8];
#pragma unroll
    for (int b = 0; b < 8; ++b) creg[b] = 0.f;
    gbar(32);

    int cur = 0;
    for (int t = 0; t < T_STEPS; ++t) {
        const float* hb = g_hbuf + cur * 4096;
        for (int e = tid; e < 4096; e += 256) h_s[e] = __ldcg(&hb[e]);
        __syncthreads();

        float acc0[8], acc1[8], acc2[8], acc3[8];
#pragma unroll
        for (int b = 0; b < 8; ++b) { acc0[b] = acc1[b] = acc2[b] = acc3[b] = 0.f; }
        const float* w0p = whh + (size_t)m * 512 + s;
        const float* w1p = whh + (size_t)(512 + m) * 512 + s;
        const float* w2p = whh + (size_t)(1024 + m) * 512 + s;
        const float* w3p = whh + (size_t)(1536 + m) * 512 + s;
#pragma unroll 4
        for (int k0 = 0; k0 < 32; ++k0) {
            int kk = k0 * 16 + s;
            float w0 = w0p[k0 * 16], w1 = w1p[k0 * 16];
            float w2 = w2p[k0 * 16], w3 = w3p[k0 * 16];
#pragma unroll
            for (int b = 0; b < 8; ++b) {
                float hv = h_s[b * 512 + kk];
                acc0[b] = fmaf(hv, w0, acc0[b]);
                acc1[b] = fmaf(hv, w1, acc1[b]);
                acc2[b] = fmaf(hv, w2, acc2[b]);
                acc3[b] = fmaf(hv, w3, acc3[b]);
            }
        }
#pragma unroll
        for (int off = 8; off; off >>= 1) {
#pragma unroll
            for (int b = 0; b < 8; ++b) {
                acc0[b] += __shfl_xor_sync(0xffffffffu, acc0[b], off);
                acc1[b] += __shfl_xor_sync(0xffffffffu, acc1[b], off);
                acc2[b] += __shfl_xor_sync(0xffffffffu, acc2[b], off);
                acc3[b] += __shfl_xor_sync(0xffffffffu, acc3[b], off);
            }
        }
        if (s == 0) {
            float* hn_buf = g_hbuf + (cur ^ 1) * 4096;
#pragma unroll
            for (int b = 0; b < 8; ++b) {
                const float* gb = g_gih + ((size_t)t * 8 + b) * 2048 + m;
                float gi = gb[0] + acc0[b];
                float gf = gb[512] + acc1[b];
                float gg = gb[1024] + acc2[b];
                float go = gb[1536] + acc3[b];
                float cn = sigm(gf) * creg[b] + sigm(gi) * tanhf(gg);
                float hn = sigm(go) * tanhf(cn);
                creg[b] = cn;
                __stcg(&hn_buf[b * 512 + m], hn);
                g_hall[((size_t)t * 8 + b) * 512 + m] = hn;
            }
        }
        cur ^= 1;
        gbar(32);
    }
}

// ---------------- K_hpart: hpart = h_all @ ow0[:, 512:].T ----------------
// rows 2048, 16/CTA, grid 128
__global__ __launch_bounds__(256) void k_hpart(const float* __restrict__ ow0) {
    __shared__ __align__(16) float a_s[16 * 512];
    int tid = threadIdx.x;
    int r0 = blockIdx.x * 16;
    const float* src = g_hall + (size_t)r0 * 512;
    for (int e = tid; e < 8192; e += 256) a_s[e] = src[e];
    __syncthreads();
    int c = tid;
    float acc[16];
#pragma unroll
    for (int i = 0; i < 16; ++i) acc[i] = 0.f;
    const float2* wr = (const float2*)(ow0 + (size_t)c * 1024 + 512);
#pragma unroll 2
    for (int k2 = 0; k2 < 256; ++k2) {
        float2 wv = wr[k2];
#pragma unroll
        for (int i = 0; i < 16; ++i) {
            float2 av = *(const float2*)&a_s[i * 512 + 2 * k2];
            acc[i] = fmaf(av.x, wv.x, acc[i]);
            acc[i] = fmaf(av.y, wv.y, acc[i]);
        }
    }
#pragma unroll
    for (int i = 0; i < 16; ++i)
        g_hpart[(size_t)(r0 + i) * 256 + c] = acc[i];
}

// ---------------- K_big: fused obs-net + emission, parallel over (t, row-tile) ----------------
// grid = 256*64, blockIdx: t = bid>>6, rb = bid&63 (16 rows each)
__global__ __launch_bounds__(256) void k_big(
    const float* __restrict__ mels, const float* __restrict__ ow1,
    const float* __restrict__ ob1, const float* __restrict__ ow2,
    const float* __restrict__ ob2, const int* __restrict__ inputs_len) {
    __shared__ __align__(16) float a1s[16 * 256];
    __shared__ __align__(16) float a2s[16 * 256];
    __shared__ __align__(16) float ps[16 * 164];
    int tid = threadIdx.x;
    int bid = blockIdx.x;
    int t = bid >> 6, rb = bid & 63;
    int r0 = rb * 16;
    int b = r0 >> 7, n0 = r0 & 127;

    const float* basep = g_base + (size_t)r0 * 256;
    const float* hp = g_hpart + ((size_t)t * 8 + b) * 256;
    for (int e = tid; e < 4096; e += 256) {
        int p = e & 255;
        a1s[e] = fmaxf(basep[e] + hp[p], 0.f);
    }
    __syncthreads();
    {   // a2 = relu(a1 @ ow1.T + ob1)
        int c = tid;
        float acc[16];
#pragma unroll
        for (int i = 0; i < 16; ++i) acc[i] = 0.f;
        const float2* wr = (const float2*)(ow1 + c * 256);
#pragma unroll 2
        for (int k2 = 0; k2 < 128; ++k2) {
            float2 wv = wr[k2];
#pragma unroll
            for (int i = 0; i < 16; ++i) {
                float2 av = *(const float2*)&a1s[i * 256 + 2 * k2];
                acc[i] = fmaf(av.x, wv.x, acc[i]);
                acc[i] = fmaf(av.y, wv.y, acc[i]);
            }
        }
        float bias = ob1[c];
#pragma unroll
        for (int i = 0; i < 16; ++i) a2s[i * 256 + c] = fmaxf(acc[i] + bias, 0.f);
    }
    __syncthreads();
    if (tid < 161) {   // p = a2 @ ow2.T + ob2
        int c = tid;
        float acc[16];
#pragma unroll
        for (int i = 0; i < 16; ++i) acc[i] = 0.f;
        const float2* wr = (const float2*)(ow2 + c * 256);
#pragma unroll 2
        for (int k2 = 0; k2 < 128; ++k2) {
            float2 wv = wr[k2];
#pragma unroll
            for (int i = 0; i < 16; ++i) {
                float2 av = *(const float2*)&a2s[i * 256 + 2 * k2];
                acc[i] = fmaf(av.x, wv.x, acc[i]);
                acc[i] = fmaf(av.y, wv.y, acc[i]);
            }
        }
        float bias = ob2[c];
#pragma unroll
        for (int i = 0; i < 16; ++i) ps[i * 164 + c] = acc[i] + bias;
    }
    __syncthreads();
    // emission: warp w handles rows 2w, 2w+1; 16 lanes per row over D=80
    {
        int w = tid >> 5, lane = tid & 31;
        int half = lane >> 4, l = lane & 15;
        int i = w * 2 + half;
        int n = n0 + i;
        float sum = 0.f;
#pragma unroll
        for (int j = 0; j < 5; ++j) {
            int d = j * 16 + l;  // d < 80 always
            float mean = ps[i * 164 + d];
            float sh = ps[i * 164 + 80 + d];
            float stdv = fmaxf(sh, 0.f) + log1pf(expf(-fabsf(sh))) + 1e-3f;
            float x = mels[(b * 80 + d) * 256 + t];
            float z = (x - mean) / stdv;
            sum += -0.5f * z * z - logf(stdv) - HALF_LOG2PI;
        }
#pragma unroll
        for (int off = 8; off; off >>= 1)
            sum += __shfl_xor_sync(0xffffffffu, sum, off);
        if (l == 0) {
            float em = (n < inputs_len[b]) ? sum : 0.f;
            g_em[((size_t)t * 8 + b) * 128 + n] = em;
            g_tv[((size_t)t * 8 + b) * 128 + n] = ps[i * 164 + 160];
        }
    }
}

// ---------------- K_hmm: sequential HMM forward, one CTA per batch ----------------
__global__ __launch_bounds__(128) void k_hmm(
    const int* __restrict__ inputs_len, const int* __restrict__ mel_lens,
    float* __restrict__ out) {
    int b = blockIdx.x;
    int n = threadIdx.x;
    __shared__ float mv[128];
    __shared__ float red[4];
    __shared__ float bc, bc2;
    int ilen = inputs_len[b], mlen = mel_lens[b];
    bool mask = n < ilen;
    float la = 0.f;
    float lp_acc = 0.f;
    float* outla = out + 8 + (size_t)b * 256 * 128;
    int wid = n >> 5, lane = n & 31;

    for (int t = 0; t < T_STEPS; ++t) {
        float em = g_em[((size_t)t * 8 + b) * 128 + n];
        float la_t;
        if (t == 0) {
            la_t = em + (n == 0 ? 0.f : NEG);
        } else {
            float tv = g_tv[((size_t)t * 8 + b) * 128 + n];
            float lstay = logf(fmaxf(1.f / (1.f + expf(tv)), 1e-4f));
            float lmove = logf(fmaxf(1.f / (1.f + expf(-tv)), 1e-4f));
            float staying = la + lstay;
            mv[n] = la + lmove;
            __syncthreads();
            float leaving = (n == 0) ? NEG : mv[n - 1];
            float mx = fmaxf(staying, leaving);
            float mn = fminf(staying, leaving);
            float outv = mx + log1pf(expf(mn - mx));
            outv = mask ? outv : NEG;
            la_t = em + outv;
        }
        // logsumexp over n
        float v = la_t;
#pragma unroll
        for (int off = 16; off; off >>= 1)
            v = fmaxf(v, __shfl_xor_sync(0xffffffffu, v, off));
        if (lane == 0) red[wid] = v;
        __syncthreads();
        if (n == 0) bc = fmaxf(fmaxf(red[0], red[1]), fmaxf(red[2], red[3]));
        __syncthreads();
        float mxa = bc;
        float ev = expf(la_t - mxa);
#pragma unroll
        for (int off = 16; off; off >>= 1)
            ev += __shfl_xor_sync(0xffffffffu, ev, off);
        if (lane == 0) red[wid] = ev;
        __syncthreads();
        if (n == 0) bc2 = mxa + logf(red[0] + red[1] + red[2] + red[3]);
        __syncthreads();
        float log_c = bc2;
        la = la_t - log_c;
        outla[(size_t)t * 128 + n] = la;
        if (t < mlen) lp_acc += log_c;
        __syncthreads();
    }
    if (n == 0) out[b] = lp_acc;
}

// ---------------- launch ----------------
extern "C" void kernel_launch(void* const* d_in, const int* in_sizes, int n_in,
                              void* d_out, int out_size) {
    const float* inputs = (const float*)d_in[0];
    const float* mels = (const float*)d_in[1];
    const float* pw0 = (const float*)d_in[2];
    const float* pw1 = (const float*)d_in[3];
    const float* wih = (const float*)d_in[4];
    const float* whh = (const float*)d_in[5];
    const float* bih = (const float*)d_in[6];
    const float* bhh = (const float*)d_in[7];
    const float* ow0 = (const float*)d_in[8];
    const float* ob0 = (const float*)d_in[9];
    const float* ow1 = (const float*)d_in[10];
    const float* ob1 = (const float*)d_in[11];
    const float* ow2 = (const float*)d_in[12];
    const float* ob2 = (const float*)d_in[13];
    const int* inputs_len = (const int*)d_in[14];
    const int* mel_lens = (const int*)d_in[15];
    float* out = (float*)d_out;

    k_prenet<<<128, 256>>>(mels, pw0, pw1, wih, bih, bhh);
    k_base<<<64, 256>>>(inputs, ow0, ob0);
    k_scan<<<32, 256>>>(whh);
    k_hpart<<<128, 256>>>(ow0);
    k_big<<<256 * 64, 256>>>(mels, ow1, ob1, ow2, ob2, inputs_len);
    k_hmm<<<8, 128>>>(inputs_len, mel_lens, out);
}

// round 3
// speedup vs baseline: 1.5624x; 1.5624x over previous
#include <cuda_runtime.h>
#include <cstdint>

#define T_STEPS 256
#define B_SZ 8
#define N_ST 128
#define E_DIM 512
#define D_DIM 80
#define M_DIM 512
#define P_DIM 256
#define NEG (-1.0e10f)
#define HALF_LOG2PI 0.9189385332046727f

// ---------------- global scratch (no allocations allowed) ----------------
__device__ float g_gih[2048 * 2048];   // (t*8+b, 2048) : pre1@W_ih.T + b_ih + b_hh
__device__ float g_base[1024 * 256];   // (b*128+n, 256): inputs@ow0[:, :512].T + ob0
__device__ float g_hall[2048 * 512];   // (t*8+b, 512)  : h_t
__device__ float g_hpart[2048 * 256];  // (t*8+b, 256)  : h@ow0[:, 512:].T
__device__ float g_hbuf[8192];         // double-buffered h state (2 x 8 x 512)
__device__ float g_em[2048 * 128];     // (t*8+b, n)
__device__ float g_tv[2048 * 128];     // (t*8+b, n)
__device__ unsigned g_cnt = 0;
__device__ unsigned g_gen = 0;

__device__ __forceinline__ float sigm(float x) { return 1.f / (1.f + expf(-x)); }

__device__ __forceinline__ void gbar(unsigned ncta) {
    __syncthreads();
    __threadfence();
    if (threadIdx.x == 0) {
        unsigned gen = *((volatile unsigned*)&g_gen);
        if (atomicAdd(&g_cnt, 1u) == ncta - 1u) {
            atomicExch(&g_cnt, 0u);
            __threadfence();
            *((volatile unsigned*)&g_gen) = gen + 1u;
        } else {
            while (*((volatile unsigned*)&g_gen) == gen) {}
        }
    }
    __syncthreads();
}

// ---------------- K_A: prenet (all t) + gates-input precompute ----------------
// rows r = t*8+b (2048), 16 rows per CTA, grid 128
__global__ __launch_bounds__(256) void k_prenet(
    const float* __restrict__ mels, const float* __restrict__ w0,
    const float* __restrict__ w1, const float* __restrict__ wih,
    const float* __restrict__ bih, const float* __restrict__ bhh) {
    __shared__ __align__(16) float in_s[16 * 80];
    __shared__ __align__(16) float p0[16 * 256];
    __shared__ __align__(16) float p1[16 * 256];
    int tid = threadIdx.x;
    int r0 = blockIdx.x * 16;

    for (int e = tid; e < 16 * 80; e += 256) {
        int i = e / 80, d = e - i * 80;
        int r = r0 + i, t = r >> 3, b = r & 7;
        in_s[e] = (t == 0) ? 0.f : mels[(b * 80 + d) * 256 + (t - 1)];
    }
    __syncthreads();
    {   // pre0 = relu(ar_x @ w0.T)   K=80
        int c = tid;
        float acc[16];
#pragma unroll
        for (int i = 0; i < 16; ++i) acc[i] = 0.f;
        const float* wr = w0 + c * 80;
        for (int k = 0; k < 80; k += 2) {
            float wa = wr[k], wb = wr[k + 1];
#pragma unroll
            for (int i = 0; i < 16; ++i) {
                acc[i] = fmaf(in_s[i * 80 + k], wa, acc[i]);
                acc[i] = fmaf(in_s[i * 80 + k + 1], wb, acc[i]);
            }
        }
#pragma unroll
        for (int i = 0; i < 16; ++i) p0[i * 256 + c] = fmaxf(acc[i], 0.f);
    }
    __syncthreads();
    {   // pre1 = relu(pre0 @ w1.T)   K=256
        int c = tid;
        float acc[16];
#pragma unroll
        for (int i = 0; i < 16; ++i) acc[i] = 0.f;
        const float2* wr = (const float2*)(w1 + c * 256);
#pragma unroll 2
        for (int k2 = 0; k2 < 128; ++k2) {
            float2 wv = wr[k2];
#pragma unroll
            for (int i = 0; i < 16; ++i) {
                float2 av = *(const float2*)&p0[i * 256 + 2 * k2];
                acc[i] = fmaf(av.x, wv.x, acc[i]);
                acc[i] = fmaf(av.y, wv.y, acc[i]);
            }
        }
#pragma unroll
        for (int i = 0; i < 16; ++i) p1[i * 256 + c] = fmaxf(acc[i], 0.f);
    }
    __syncthreads();
    // gih = pre1 @ wih.T + b_ih + b_hh   (2048 cols, 8 col-blocks)
    for (int cb = 0; cb < 8; ++cb) {
        int col = cb * 256 + tid;
        float acc[16];
#pragma unroll
        for (int i = 0; i < 16; ++i) acc[i] = 0.f;
        const float2* wr = (const float2*)(wih + (size_t)col * 256);
#pragma unroll 2
        for (int k2 = 0; k2 < 128; ++k2) {
            float2 wv = wr[k2];
#pragma unroll
            for (int i = 0; i < 16; ++i) {
                float2 av = *(const float2*)&p1[i * 256 + 2 * k2];
                acc[i] = fmaf(av.x, wv.x, acc[i]);
                acc[i] = fmaf(av.y, wv.y, acc[i]);
            }
        }
        float bias = bih[col] + bhh[col];
#pragma unroll
        for (int i = 0; i < 16; ++i)
            g_gih[(size_t)(r0 + i) * 2048 + col] = acc[i] + bias;
    }
}

// ---------------- K_base: base = inputs @ ow0[:, :512].T + ob0 ----------------
// rows 1024, 16/CTA, grid 64
__global__ __launch_bounds__(256) void k_base(
    const float* __restrict__ inputs, const float* __restrict__ ow0,
    const float* __restrict__ ob0) {
    __shared__ __align__(16) float a_s[16 * 512];
    int tid = threadIdx.x;
    int r0 = blockIdx.x * 16;
    const float* src = inputs + (size_t)r0 * 512;
    for (int e = tid; e < 8192; e += 256) a_s[e] = src[e];
    __syncthreads();
    int c = tid;
    float acc[16];
#pragma unroll
    for (int i = 0; i < 16; ++i) acc[i] = 0.f;
    const float2* wr = (const float2*)(ow0 + (size_t)c * 1024);
#pragma unroll 2
    for (int k2 = 0; k2 < 256; ++k2) {
        float2 wv = wr[k2];
#pragma unroll
        for (int i = 0; i < 16; ++i) {
            float2 av = *(const float2*)&a_s[i * 512 + 2 * k2];
            acc[i] = fmaf(av.x, wv.x, acc[i]);
            acc[i] = fmaf(av.y, wv.y, acc[i]);
        }
    }
    float bias = ob0[c];
#pragma unroll
    for (int i = 0; i < 16; ++i)
        g_base[(size_t)(r0 + i) * 256 + c] = acc[i] + bias;
}

// ---------------- K_scan: sequential LSTM over T with grid barrier ----------------
// grid MUST be 32 CTAs x 256 thr (8192 threads = 512 units x 16 k-slices)
__global__ __launch_bounds__(256) void k_scan(const float* __restrict__ whh) {
    __shared__ float h_s[4096];
    int tid = threadIdx.x;
    int gt = blockIdx.x * 256 + tid;
    int m = gt >> 4, s = gt & 15;

    if (gt < 8192) g_hbuf[gt] = 0.f;   // zero both h buffers
    float creg[8];
#pragma unroll
    for (int b = 0; b < 8; ++b) creg[b] = 0.f;
    gbar(32);

    int cur = 0;
    for (int t = 0; t < T_STEPS; ++t) {
        const float* hb = g_hbuf + cur * 4096;
        for (int e = tid; e < 4096; e += 256) h_s[e] = __ldcg(&hb[e]);
        __syncthreads();

        float acc0[8], acc1[8], acc2[8], acc3[8];
#pragma unroll
        for (int b = 0; b < 8; ++b) { acc0[b] = acc1[b] = acc2[b] = acc3[b] = 0.f; }
        const float* w0p = whh + (size_t)m * 512 + s;
        const float* w1p = whh + (size_t)(512 + m) * 512 + s;
        const float* w2p = whh + (size_t)(1024 + m) * 512 + s;
        const float* w3p = whh + (size_t)(1536 + m) * 512 + s;
#pragma unroll 4
        for (int k0 = 0; k0 < 32; ++k0) {
            int kk = k0 * 16 + s;
            float w0 = w0p[k0 * 16], w1 = w1p[k0 * 16];
            float w2 = w2p[k0 * 16], w3 = w3p[k0 * 16];
#pragma unroll
            for (int b = 0; b < 8; ++b) {
                float hv = h_s[b * 512 + kk];
                acc0[b] = fmaf(hv, w0, acc0[b]);
                acc1[b] = fmaf(hv, w1, acc1[b]);
                acc2[b] = fmaf(hv, w2, acc2[b]);
                acc3[b] = fmaf(hv, w3, acc3[b]);
            }
        }
#pragma unroll
        for (int off = 8; off; off >>= 1) {
#pragma unroll
            for (int b = 0; b < 8; ++b) {
                acc0[b] += __shfl_xor_sync(0xffffffffu, acc0[b], off);
                acc1[b] += __shfl_xor_sync(0xffffffffu, acc1[b], off);
                acc2[b] += __shfl_xor_sync(0xffffffffu, acc2[b], off);
                acc3[b] += __shfl_xor_sync(0xffffffffu, acc3[b], off);
            }
        }
        if (s == 0) {
            float* hn_buf = g_hbuf + (cur ^ 1) * 4096;
#pragma unroll
            for (int b = 0; b < 8; ++b) {
                const float* gb = g_gih + ((size_t)t * 8 + b) * 2048 + m;
                float gi = gb[0] + acc0[b];
                float gf = gb[512] + acc1[b];
                float gg = gb[1024] + acc2[b];
                float go = gb[1536] + acc3[b];
                float cn = sigm(gf) * creg[b] + sigm(gi) * tanhf(gg);
                float hn = sigm(go) * tanhf(cn);
                creg[b] = cn;
                __stcg(&hn_buf[b * 512 + m], hn);
                g_hall[((size_t)t * 8 + b) * 512 + m] = hn;
            }
        }
        cur ^= 1;
        gbar(32);
    }
}

// ---------------- K_hpart: hpart = h_all @ ow0[:, 512:].T ----------------
// rows 2048, 16/CTA, grid 128
__global__ __launch_bounds__(256) void k_hpart(const float* __restrict__ ow0) {
    __shared__ __align__(16) float a_s[16 * 512];
    int tid = threadIdx.x;
    int r0 = blockIdx.x * 16;
    const float* src = g_hall + (size_t)r0 * 512;
    for (int e = tid; e < 8192; e += 256) a_s[e] = src[e];
    __syncthreads();
    int c = tid;
    float acc[16];
#pragma unroll
    for (int i = 0; i < 16; ++i) acc[i] = 0.f;
    const float2* wr = (const float2*)(ow0 + (size_t)c * 1024 + 512);
#pragma unroll 2
    for (int k2 = 0; k2 < 256; ++k2) {
        float2 wv = wr[k2];
#pragma unroll
        for (int i = 0; i < 16; ++i) {
            float2 av = *(const float2*)&a_s[i * 512 + 2 * k2];
            acc[i] = fmaf(av.x, wv.x, acc[i]);
            acc[i] = fmaf(av.y, wv.y, acc[i]);
        }
    }
#pragma unroll
    for (int i = 0; i < 16; ++i)
        g_hpart[(size_t)(r0 + i) * 256 + c] = acc[i];
}

// ---------------- K_big: fused obs-net + emission, parallel over (t, row-tile) ----------------
// grid = 256*64, blockIdx: t = bid>>6, rb = bid&63 (16 rows each)
__global__ __launch_bounds__(256) void k_big(
    const float* __restrict__ mels, const float* __restrict__ ow1,
    const float* __restrict__ ob1, const float* __restrict__ ow2,
    const float* __restrict__ ob2, const int* __restrict__ inputs_len) {
    __shared__ __align__(16) float a1s[16 * 256];
    __shared__ __align__(16) float a2s[16 * 256];
    __shared__ __align__(16) float ps[16 * 164];
    int tid = threadIdx.x;
    int bid = blockIdx.x;
    int t = bid >> 6, rb = bid & 63;
    int r0 = rb * 16;
    int b = r0 >> 7, n0 = r0 & 127;

    const float* basep = g_base + (size_t)r0 * 256;
    const float* hp = g_hpart + ((size_t)t * 8 + b) * 256;
    for (int e = tid; e < 4096; e += 256) {
        int p = e & 255;
        a1s[e] = fmaxf(basep[e] + hp[p], 0.f);
    }
    __syncthreads();
    {   // a2 = relu(a1 @ ow1.T + ob1)
        int c = tid;
        float acc[16];
#pragma unroll
        for (int i = 0; i < 16; ++i) acc[i] = 0.f;
        const float2* wr = (const float2*)(ow1 + c * 256);
#pragma unroll 2
        for (int k2 = 0; k2 < 128; ++k2) {
            float2 wv = wr[k2];
#pragma unroll
            for (int i = 0; i < 16; ++i) {
                float2 av = *(const float2*)&a1s[i * 256 + 2 * k2];
                acc[i] = fmaf(av.x, wv.x, acc[i]);
                acc[i] = fmaf(av.y, wv.y, acc[i]);
            }
        }
        float bias = ob1[c];
#pragma unroll
        for (int i = 0; i < 16; ++i) a2s[i * 256 + c] = fmaxf(acc[i] + bias, 0.f);
    }
    __syncthreads();
    if (tid < 161) {   // p = a2 @ ow2.T + ob2
        int c = tid;
        float acc[16];
#pragma unroll
        for (int i = 0; i < 16; ++i) acc[i] = 0.f;
        const float2* wr = (const float2*)(ow2 + c * 256);
#pragma unroll 2
        for (int k2 = 0; k2 < 128; ++k2) {
            float2 wv = wr[k2];
#pragma unroll
            for (int i = 0; i < 16; ++i) {
                float2 av = *(const float2*)&a2s[i * 256 + 2 * k2];
                acc[i] = fmaf(av.x, wv.x, acc[i]);
                acc[i] = fmaf(av.y, wv.y, acc[i]);
            }
        }
        float bias = ob2[c];
#pragma unroll
        for (int i = 0; i < 16; ++i) ps[i * 164 + c] = acc[i] + bias;
    }
    __syncthreads();
    // emission: warp w handles rows 2w, 2w+1; 16 lanes per row over D=80
    {
        int w = tid >> 5, lane = tid & 31;
        int half = lane >> 4, l = lane & 15;
        int i = w * 2 + half;
        int n = n0 + i;
        float sum = 0.f;
#pragma unroll
        for (int j = 0; j < 5; ++j) {
            int d = j * 16 + l;  // d < 80 always
            float mean = ps[i * 164 + d];
            float sh = ps[i * 164 + 80 + d];
            float stdv = fmaxf(sh, 0.f) + log1pf(expf(-fabsf(sh))) + 1e-3f;
            float x = mels[(b * 80 + d) * 256 + t];
            float z = (x - mean) / stdv;
            sum += -0.5f * z * z - logf(stdv) - HALF_LOG2PI;
        }
#pragma unroll
        for (int off = 8; off; off >>= 1)
            sum += __shfl_xor_sync(0xffffffffu, sum, off);
        if (l == 0) {
            float em = (n < inputs_len[b]) ? sum : 0.f;
            g_em[((size_t)t * 8 + b) * 128 + n] = em;
            g_tv[((size_t)t * 8 + b) * 128 + n] = ps[i * 164 + 160];
        }
    }
}

// ---------------- K_hmm: sequential HMM forward, one CTA per batch ----------------
__global__ __launch_bounds__(128) void k_hmm(
    const int* __restrict__ inputs_len, const int* __restrict__ mel_lens,
    float* __restrict__ out) {
    int b = blockIdx.x;
    int n = threadIdx.x;
    __shared__ float mv[128];
    __shared__ float red[4];
    __shared__ float bc, bc2;
    int ilen = inputs_len[b], mlen = mel_lens[b];
    bool mask = n < ilen;
    float la = 0.f;
    float lp_acc = 0.f;
    float* outla = out + 8 + (size_t)b * 256 * 128;
    int wid = n >> 5, lane = n & 31;

    for (int t = 0; t < T_STEPS; ++t) {
        float em = g_em[((size_t)t * 8 + b) * 128 + n];
        float la_t;
        if (t == 0) {
            la_t = em + (n == 0 ? 0.f : NEG);
        } else {
            float tv = g_tv[((size_t)t * 8 + b) * 128 + n];
            float lstay = logf(fmaxf(1.f / (1.f + expf(tv)), 1e-4f));
            float lmove = logf(fmaxf(1.f / (1.f + expf(-tv)), 1e-4f));
            float staying = la + lstay;
            mv[n] = la + lmove;
            __syncthreads();
            float leaving = (n == 0) ? NEG : mv[n - 1];
            float mx = fmaxf(staying, leaving);
            float mn = fminf(staying, leaving);
            float outv = mx + log1pf(expf(mn - mx));
            outv = mask ? outv : NEG;
            la_t = em + outv;
        }
        // logsumexp over n
        float v = la_t;
#pragma unroll
        for (int off = 16; off; off >>= 1)
            v = fmaxf(v, __shfl_xor_sync(0xffffffffu, v, off));
        if (lane == 0) red[wid] = v;
        __syncthreads();
        if (n == 0) bc = fmaxf(fmaxf(red[0], red[1]), fmaxf(red[2], red[3]));
        __syncthreads();
        float mxa = bc;
        float ev = expf(la_t - mxa);
#pragma unroll
        for (int off = 16; off; off >>= 1)
            ev += __shfl_xor_sync(0xffffffffu, ev, off);
        if (lane == 0) red[wid] = ev;
        __syncthreads();
        if (n == 0) bc2 = mxa + logf(red[0] + red[1] + red[2] + red[3]);
        __syncthreads();
        float log_c = bc2;
        la = la_t - log_c;
        outla[(size_t)t * 128 + n] = la;
        if (t < mlen) lp_acc += log_c;
        __syncthreads();
    }
    if (n == 0) out[b] = lp_acc;
}

// ---------------- launch ----------------
extern "C" void kernel_launch(void* const* d_in, const int* in_sizes, int n_in,
                              void* d_out, int out_size) {
    const float* inputs = (const float*)d_in[0];
    const float* mels = (const float*)d_in[1];
    const float* pw0 = (const float*)d_in[2];
    const float* pw1 = (const float*)d_in[3];
    const float* wih = (const float*)d_in[4];
    const float* whh = (const float*)d_in[5];
    const float* bih = (const float*)d_in[6];
    const float* bhh = (const float*)d_in[7];
    const float* ow0 = (const float*)d_in[8];
    const float* ob0 = (const float*)d_in[9];
    const float* ow1 = (const float*)d_in[10];
    const float* ob1 = (const float*)d_in[11];
    const float* ow2 = (const float*)d_in[12];
    const float* ob2 = (const float*)d_in[13];
    const int* inputs_len = (const int*)d_in[14];
    const int* mel_lens = (const int*)d_in[15];
    float* out = (float*)d_out;

    k_prenet<<<128, 256>>>(mels, pw0, pw1, wih, bih, bhh);
    k_base<<<64, 256>>>(inputs, ow0, ob0);
    k_scan<<<32, 256>>>(whh);
    k_hpart<<<128, 256>>>(ow0);
    k_big<<<256 * 64, 256>>>(mels, ow1, ob1, ow2, ob2, inputs_len);
    k_hmm<<<8, 128>>>(inputs_len, mel_lens, out);
}

// round 4
// speedup vs baseline: 3.4643x; 2.2172x over previous
#include <cuda_runtime.h>
#include <cstdint>

#define T_STEPS 256
#define NEG (-1.0e10f)
#define HALF_LOG2PI 0.9189385332046727f
typedef unsigned long long u64;

// ---------------- global scratch ----------------
__device__ float g_arwin[2048 * 96];
__device__ float g_w0p[256 * 96];
__device__ float g_pre[2048 * 256];
__device__ float g_gih[2048 * 2048];
__device__ float g_base[1024 * 256];
__device__ float g_hall[2048 * 512];
__device__ float g_hpart[2048 * 256];   // also reused as p0 scratch
__device__ float g_hbuf[8192];
__device__ float g_em[2048 * 128];
__device__ float g_tv[2048 * 128];
__device__ unsigned g_cnt = 0;
__device__ unsigned g_gen = 0;

// ---------------- helpers ----------------
__device__ __forceinline__ u64 pk2(float x) {
    u64 r; asm("mov.b64 %0, {%1, %1};" : "=l"(r) : "f"(x)); return r;
}
__device__ __forceinline__ u64 pkxy(float x, float y) {
    u64 r; asm("mov.b64 %0, {%1, %2};" : "=l"(r) : "f"(x), "f"(y)); return r;
}
__device__ __forceinline__ void fma2(u64& d, u64 a, u64 b) {
    asm("fma.rn.f32x2 %0, %1, %2, %0;" : "+l"(d) : "l"(a), "l"(b));
}
__device__ __forceinline__ float2 up2(u64 v) {
    float2 f; asm("mov.b64 {%0, %1}, %2;" : "=f"(f.x), "=f"(f.y) : "l"(v)); return f;
}
__device__ __forceinline__ float sigm(float x) { return 1.f / (1.f + expf(-x)); }

__device__ __forceinline__ void gbar(unsigned ncta) {
    __syncthreads();
    __threadfence();
    if (threadIdx.x == 0) {
        unsigned gen = *((volatile unsigned*)&g_gen);
        if (atomicAdd(&g_cnt, 1u) == ncta - 1u) {
            atomicExch(&g_cnt, 0u);
            __threadfence();
            *((volatile unsigned*)&g_gen) = gen + 1u;
        } else {
            while (*((volatile unsigned*)&g_gen) == gen) {}
        }
    }
    __syncthreads();
}

// 8-row x (NJ*64)-col micro step, one k. Ap -> As[k][ty*8], Bp -> Bs + k*128.
template <int NJ>
__device__ __forceinline__ void mk8(const float* __restrict__ Ap,
                                    const u64* __restrict__ Bp, int lane, u64* acc) {
    float4 a0 = *(const float4*)Ap;
    float4 a1 = *(const float4*)(Ap + 4);
    u64 bv[NJ];
#pragma unroll
    for (int j = 0; j < NJ; ++j) bv[j] = Bp[j * 32 + lane];
    float av[8] = {a0.x, a0.y, a0.z, a0.w, a1.x, a1.y, a1.z, a1.w};
#pragma unroll
    for (int i = 0; i < 8; ++i) {
        u64 ap = pk2(av[i]);
#pragma unroll
        for (int j = 0; j < NJ; ++j) fma2(acc[i * NJ + j], ap, bv[j]);
    }
}

// Pack 32-k chunk of W rows (col-pairs c, c+32) into Bs as f32x2.
template <int NJ>
__device__ __forceinline__ void loadB(const float* __restrict__ W, int ldw, int c0,
                                      int k0, int wmax, u64* Bs, int tid) {
    if (tid < NJ * 32) {
        int j = tid >> 5, p = tid & 31;
        int ca = c0 + p + 64 * j; if (ca > wmax) ca = wmax;
        int cb = c0 + p + 32 + 64 * j; if (cb > wmax) cb = wmax;
        const float* wa = W + (size_t)ca * ldw + k0;
        const float* wb = W + (size_t)cb * ldw + k0;
        u64* dst = Bs + j * 32 + p;
#pragma unroll
        for (int k = 0; k < 32; k += 4) {
            float4 va = *(const float4*)(wa + k);
            float4 vb = *(const float4*)(wb + k);
            dst[(k + 0) * 128] = pkxy(va.x, vb.x);
            dst[(k + 1) * 128] = pkxy(va.y, vb.y);
            dst[(k + 2) * 128] = pkxy(va.z, vb.z);
            dst[(k + 3) * 128] = pkxy(va.w, vb.w);
        }
    }
}

// ---------------- k_prep: padded ar_win + padded w0 ----------------
__global__ __launch_bounds__(256) void k_prep(const float* __restrict__ mels,
                                              const float* __restrict__ w0) {
    int i = blockIdx.x * 256 + threadIdx.x;
    int stride = gridDim.x * 256;
    for (int e = i; e < 2048 * 96; e += stride) {
        int r = e / 96, k = e - r * 96;
        int t = r >> 3, b = r & 7;
        g_arwin[e] = (k < 80 && t > 0) ? mels[((size_t)b * 80 + k) * 256 + t - 1] : 0.f;
    }
    for (int e = i; e < 256 * 96; e += stride) {
        int c = e / 96, k = e - c * 96;
        g_w0p[e] = (k < 80) ? w0[c * 80 + k] : 0.f;
    }
}

// ---------------- generic GEMM: C[64x256 tile] = A @ W^T (+b1+b2, relu) ----------------
__global__ __launch_bounds__(256) void k_gemm(
    const float* __restrict__ A, int lda, int K,
    const float* __restrict__ W, int ldw, int wmax,
    const float* __restrict__ b1, const float* __restrict__ b2,
    float* __restrict__ C, int ldc, int relu) {
    __shared__ __align__(16) float As[32 * 68];
    __shared__ __align__(16) u64 Bs[32 * 128];
    int tid = threadIdx.x;
    int r0 = blockIdx.x * 64, c0 = blockIdx.y * 256;
    int ty = tid >> 5, lane = tid & 31;
    u64 acc[32];
#pragma unroll
    for (int i = 0; i < 32; ++i) acc[i] = 0ull;
    int ar = tid & 63, akq = (tid >> 6) * 8;
    const float* Arow = A + (size_t)(r0 + ar) * lda + akq;
    for (int k0 = 0; k0 < K; k0 += 32) {
        float4 v0 = *(const float4*)(Arow + k0);
        float4 v1 = *(const float4*)(Arow + k0 + 4);
        As[(akq + 0) * 68 + ar] = v0.x; As[(akq + 1) * 68 + ar] = v0.y;
        As[(akq + 2) * 68 + ar] = v0.z; As[(akq + 3) * 68 + ar] = v0.w;
        As[(akq + 4) * 68 + ar] = v1.x; As[(akq + 5) * 68 + ar] = v1.y;
        As[(akq + 6) * 68 + ar] = v1.z; As[(akq + 7) * 68 + ar] = v1.w;
        loadB<4>(W, ldw, c0, k0, wmax, Bs, tid);
        __syncthreads();
#pragma unroll 4
        for (int kk = 0; kk < 32; ++kk)
            mk8<4>(As + kk * 68 + ty * 8, Bs + kk * 128, lane, acc);
        __syncthreads();
    }
#pragma unroll
    for (int j = 0; j < 4; ++j) {
        int ca = c0 + j * 64 + lane, cb = ca + 32;
        float bba = (b1 ? b1[ca] : 0.f) + (b2 ? b2[ca] : 0.f);
        float bbb = (b1 ? b1[cb] : 0.f) + (b2 ? b2[cb] : 0.f);
#pragma unroll
        for (int i = 0; i < 8; ++i) {
            float2 v = up2(acc[i * 4 + j]);
            float x = v.x + bba, y = v.y + bbb;
            if (relu) { x = fmaxf(x, 0.f); y = fmaxf(y, 0.f); }
            float* cr = C + (size_t)(r0 + ty * 8 + i) * ldc;
            cr[ca] = x; cr[cb] = y;
        }
    }
}

// ---------------- k_scan: LSTM recurrence, 64 CTAs, weights resident in smem ----------------
// dyn smem: wsm[32][516] + hs[8][516]
__global__ __launch_bounds__(256) void k_scan(const float* __restrict__ whh) {
    extern __shared__ float sm[];
    float* wsm = sm;
    float* hs = sm + 32 * 516;
    int tid = threadIdx.x, cta = blockIdx.x;
    int mbase = cta * 8;
    {   // load weight slice: rows {g*512 + mbase + ml}
        int rowid = tid >> 3, seg = tid & 7;
        int g = rowid & 3, ml = rowid >> 2;
        const float* src = whh + (size_t)(g * 512 + mbase + ml) * 512 + seg * 64;
        float* dst = wsm + rowid * 516 + seg * 64;
#pragma unroll
        for (int q = 0; q < 64; q += 4) *(float4*)(dst + q) = *(const float4*)(src + q);
    }
    int gt = cta * 256 + tid;
    if (gt < 8192) g_hbuf[gt] = 0.f;

    int b = tid & 7, gate = (tid >> 3) & 3, ml = tid >> 5;
    int m = mbase + ml;
    float cst = 0.f;
    gbar(64);

    int cur = 0;
    for (int t = 0; t < T_STEPS; ++t) {
        float gihv0 = 0.f, gihv1 = 0.f, gihv2 = 0.f, gihv3 = 0.f;
        if (gate == 0) {
            const float* gp = g_gih + ((size_t)t * 8 + b) * 2048 + m;
            gihv0 = __ldg(gp); gihv1 = __ldg(gp + 512);
            gihv2 = __ldg(gp + 1024); gihv3 = __ldg(gp + 1536);
        }
        {   // copy h into smem (L1-bypassing loads; written with stcg)
            int bb = tid >> 5, k0 = (tid & 31) * 16;
            const float4* src = (const float4*)(g_hbuf + cur * 4096 + bb * 512 + k0);
            float* dst = hs + bb * 516 + k0;
#pragma unroll
            for (int q = 0; q < 4; ++q) *(float4*)(dst + q * 4) = __ldcg(src + q);
        }
        __syncthreads();
        u64 acc = 0ull;
        const float* wr = wsm + (ml * 4 + gate) * 516;
        const float* hr = hs + b * 516;
#pragma unroll 8
        for (int k = 0; k < 512; k += 8) {
            ulonglong2 wa = *(const ulonglong2*)(wr + k);
            ulonglong2 wb = *(const ulonglong2*)(wr + k + 4);
            ulonglong2 ha = *(const ulonglong2*)(hr + k);
            ulonglong2 hb = *(const ulonglong2*)(hr + k + 4);
            fma2(acc, wa.x, ha.x); fma2(acc, wa.y, ha.y);
            fma2(acc, wb.x, hb.x); fma2(acc, wb.y, hb.y);
        }
        float2 dv = up2(acc);
        float dot = dv.x + dv.y;
        int lb = tid & 7;  // lane = gate*8 + b within warp
        float d0 = __shfl_sync(0xffffffffu, dot, lb + 0);
        float d1 = __shfl_sync(0xffffffffu, dot, lb + 8);
        float d2 = __shfl_sync(0xffffffffu, dot, lb + 16);
        float d3 = __shfl_sync(0xffffffffu, dot, lb + 24);
        if (gate == 0) {
            float gi = gihv0 + d0, gf = gihv1 + d1, gg = gihv2 + d2, go = gihv3 + d3;
            float cn = sigm(gf) * cst + sigm(gi) * tanhf(gg);
            float hn = sigm(go) * tanhf(cn);
            cst = cn;
            __stcg(&g_hbuf[(cur ^ 1) * 4096 + b * 512 + m], hn);
            g_hall[((size_t)t * 8 + b) * 512 + m] = hn;
        }
        cur ^= 1;
        gbar(64);
    }
}

// ---------------- k_big: fused obs-net + emission ----------------
// grid 4096: t = bid>>4, rowtile = bid&15 (64 rows). dyn smem: As 256x68 + Bs 32x128 u64
#define BIG_SMEM (256 * 68 * 4 + 32 * 128 * 8)
__global__ __launch_bounds__(256) void k_big(
    const float* __restrict__ mels, const float* __restrict__ ow1,
    const float* __restrict__ ob1, const float* __restrict__ ow2,
    const float* __restrict__ ob2, const int* __restrict__ inputs_len) {
    extern __shared__ char smraw[];
    float* As = (float*)smraw;
    u64* Bs = (u64*)(smraw + 256 * 68 * 4);
    __shared__ float xs[80];
    __shared__ int ilen_s;
    int tid = threadIdx.x, bid = blockIdx.x;
    int t = bid >> 4, rt = bid & 15;
    int r0 = rt * 64;
    int b = r0 >> 7, n0 = r0 & 127;
    int ty = tid >> 5, lane = tid & 31;

    if (tid < 80) xs[tid] = mels[((size_t)b * 80 + tid) * 256 + t];
    if (tid == 80) ilen_s = inputs_len[b];
    {   // A1 = relu(base + hpart), transposed into As[k][row]
        int r = tid & 63;
        const float* bp = g_base + (size_t)(r0 + r) * 256;
        const float* hp = g_hpart + ((size_t)t * 8 + b) * 256;
        for (int kq = (tid >> 6) * 8; kq < 256; kq += 32) {
            float4 v0 = *(const float4*)(bp + kq);
            float4 v1 = *(const float4*)(bp + kq + 4);
            float4 h0 = *(const float4*)(hp + kq);
            float4 h1 = *(const float4*)(hp + kq + 4);
            As[(kq + 0) * 68 + r] = fmaxf(v0.x + h0.x, 0.f);
            As[(kq + 1) * 68 + r] = fmaxf(v0.y + h0.y, 0.f);
            As[(kq + 2) * 68 + r] = fmaxf(v0.z + h0.z, 0.f);
            As[(kq + 3) * 68 + r] = fmaxf(v0.w + h0.w, 0.f);
            As[(kq + 4) * 68 + r] = fmaxf(v1.x + h1.x, 0.f);
            As[(kq + 5) * 68 + r] = fmaxf(v1.y + h1.y, 0.f);
            As[(kq + 6) * 68 + r] = fmaxf(v1.z + h1.z, 0.f);
            As[(kq + 7) * 68 + r] = fmaxf(v1.w + h1.w, 0.f);
        }
    }
    // stage 1: a2 = relu(a1 @ ow1^T + ob1), 256 cols
    u64 acc[32];
#pragma unroll
    for (int i = 0; i < 32; ++i) acc[i] = 0ull;
    for (int ch = 0; ch < 8; ++ch) {
        int k0 = ch * 32;
        loadB<4>(ow1, 256, 0, k0, 255, Bs, tid);
        __syncthreads();
#pragma unroll 4
        for (int kk = 0; kk < 32; ++kk)
            mk8<4>(As + (k0 + kk) * 68 + ty * 8, Bs + kk * 128, lane, acc);
        __syncthreads();
    }
    // write a2 transposed back into As
#pragma unroll
    for (int j = 0; j < 4; ++j) {
        int ca = j * 64 + lane, cb = ca + 32;
        float ba = ob1[ca], bb = ob1[cb];
#pragma unroll
        for (int i = 0; i < 8; ++i) {
            float2 v = up2(acc[i * 4 + j]);
            As[ca * 68 + ty * 8 + i] = fmaxf(v.x + ba, 0.f);
            As[cb * 68 + ty * 8 + i] = fmaxf(v.y + bb, 0.f);
        }
    }
    __syncthreads();
    // stage 2: p = a2 @ ow2^T + ob2, 161 cols (NJ=3 -> 192)
    u64 acc2[24];
#pragma unroll
    for (int i = 0; i < 24; ++i) acc2[i] = 0ull;
    for (int ch = 0; ch < 8; ++ch) {
        int k0 = ch * 32;
        loadB<3>(ow2, 256, 0, k0, 160, Bs, tid);
        __syncthreads();
#pragma unroll 4
        for (int kk = 0; kk < 32; ++kk)
            mk8<3>(As + (k0 + kk) * 68 + ty * 8, Bs + kk * 128, lane, acc2);
        __syncthreads();
    }
    float* ps = As;  // overlay (64 x 164)
#pragma unroll
    for (int j = 0; j < 3; ++j) {
        int ca = j * 64 + lane, cb = ca + 32;
        float ba = (ca < 161) ? ob2[ca] : 0.f;
        float bb = (cb < 161) ? ob2[cb] : 0.f;
#pragma unroll
        for (int i = 0; i < 8; ++i) {
            float2 v = up2(acc2[i * 3 + j]);
            if (ca < 161) ps[(ty * 8 + i) * 164 + ca] = v.x + ba;
            if (cb < 161) ps[(ty * 8 + i) * 164 + cb] = v.y + bb;
        }
    }
    __syncthreads();
    // emission: warp ty -> rows ty*8..+8; lane: row = lane>>2, d-part = lane&3 (20 d each)
    {
        int ri = lane >> 2, part = lane & 3;
        int row = ty * 8 + ri;
        const float* pr = ps + row * 164;
        float sum = 0.f;
        int dend = part * 20 + 20;
        for (int d = part * 20; d < dend; ++d) {
            float mean = pr[d], sh = pr[80 + d];
            float stdv = fmaxf(sh, 0.f) + log1pf(expf(-fabsf(sh))) + 1e-3f;
            float z = (xs[d] - mean) / stdv;
            sum += -0.5f * z * z - logf(stdv) - HALF_LOG2PI;
        }
        sum += __shfl_xor_sync(0xffffffffu, sum, 1);
        sum += __shfl_xor_sync(0xffffffffu, sum, 2);
        if (part == 0) {
            int n = n0 + row;
            g_em[((size_t)t * 8 + b) * 128 + n] = (n < ilen_s) ? sum : 0.f;
            g_tv[((size_t)t * 8 + b) * 128 + n] = pr[160];
        }
    }
}

// ---------------- k_hmm: sequential HMM forward, one CTA per batch ----------------
__global__ __launch_bounds__(128) void k_hmm(
    const int* __restrict__ inputs_len, const int* __restrict__ mel_lens,
    float* __restrict__ out) {
    int b = blockIdx.x;
    int n = threadIdx.x;
    __shared__ float mv[128];
    __shared__ float red[4];
    __shared__ float bc, bc2;
    int ilen = inputs_len[b], mlen = mel_lens[b];
    bool mask = n < ilen;
    float la = 0.f, lp_acc = 0.f;
    float* outla = out + 8 + (size_t)b * 256 * 128;
    int wid = n >> 5, lane = n & 31;

    for (int t = 0; t < T_STEPS; ++t) {
        float em = g_em[((size_t)t * 8 + b) * 128 + n];
        float la_t;
        if (t == 0) {
            la_t = em + (n == 0 ? 0.f : NEG);
        } else {
            float tv = g_tv[((size_t)t * 8 + b) * 128 + n];
            float lstay = logf(fmaxf(1.f / (1.f + expf(tv)), 1e-4f));
            float lmove = logf(fmaxf(1.f / (1.f + expf(-tv)), 1e-4f));
            float staying = la + lstay;
            mv[n] = la + lmove;
            __syncthreads();
            float leaving = (n == 0) ? NEG : mv[n - 1];
            float mx = fmaxf(staying, leaving);
            float mn = fminf(staying, leaving);
            float outv = mx + log1pf(expf(mn - mx));
            outv = mask ? outv : NEG;
            la_t = em + outv;
        }
        float v = la_t;
#pragma unroll
        for (int off = 16; off; off >>= 1)
            v = fmaxf(v, __shfl_xor_sync(0xffffffffu, v, off));
        if (lane == 0) red[wid] = v;
        __syncthreads();
        if (n == 0) bc = fmaxf(fmaxf(red[0], red[1]), fmaxf(red[2], red[3]));
        __syncthreads();
        float mxa = bc;
        float ev = expf(la_t - mxa);
#pragma unroll
        for (int off = 16; off; off >>= 1)
            ev += __shfl_xor_sync(0xffffffffu, ev, off);
        if (lane == 0) red[wid] = ev;
        __syncthreads();
        if (n == 0) bc2 = mxa + logf(red[0] + red[1] + red[2] + red[3]);
        __syncthreads();
        float log_c = bc2;
        la = la_t - log_c;
        outla[(size_t)t * 128 + n] = la;
        if (t < mlen) lp_acc += log_c;
        __syncthreads();
    }
    if (n == 0) out[b] = lp_acc;
}

// ---------------- launch ----------------
#define SCAN_SMEM ((32 + 8) * 516 * 4)

extern "C" void kernel_launch(void* const* d_in, const int* in_sizes, int n_in,
                              void* d_out, int out_size) {
    const float* inputs = (const float*)d_in[0];
    const float* mels = (const float*)d_in[1];
    const float* pw0 = (const float*)d_in[2];
    const float* pw1 = (const float*)d_in[3];
    const float* wih = (const float*)d_in[4];
    const float* whh = (const float*)d_in[5];
    const float* bih = (const float*)d_in[6];
    const float* bhh = (const float*)d_in[7];
    const float* ow0 = (const float*)d_in[8];
    const float* ob0 = (const float*)d_in[9];
    const float* ow1 = (const float*)d_in[10];
    const float* ob1 = (const float*)d_in[11];
    const float* ow2 = (const float*)d_in[12];
    const float* ob2 = (const float*)d_in[13];
    const int* inputs_len = (const int*)d_in[14];
    const int* mel_lens = (const int*)d_in[15];
    float* out = (float*)d_out;

    cudaFuncSetAttribute(k_scan, cudaFuncAttributeMaxDynamicSharedMemorySize, SCAN_SMEM);
    cudaFuncSetAttribute(k_big, cudaFuncAttributeMaxDynamicSharedMemorySize, BIG_SMEM);

    float *arwin, *w0p, *pre, *base, *hall, *hpart;
    cudaGetSymbolAddress((void**)&arwin, g_arwin);
    cudaGetSymbolAddress((void**)&w0p, g_w0p);
    cudaGetSymbolAddress((void**)&pre, g_pre);
    cudaGetSymbolAddress((void**)&base, g_base);
    cudaGetSymbolAddress((void**)&hall, g_hall);
    cudaGetSymbolAddress((void**)&hpart, g_hpart);
    float* gih; cudaGetSymbolAddress((void**)&gih, g_gih);

    k_prep<<<192, 256>>>(mels, pw0);
    // p0 = relu(arwin @ w0p^T)  -> g_hpart (scratch)
    k_gemm<<<dim3(32, 1), 256>>>(arwin, 96, 96, w0p, 96, 255, nullptr, nullptr, hpart, 256, 1);
    // pre1 = relu(p0 @ pw1^T) -> g_pre
    k_gemm<<<dim3(32, 1), 256>>>(hpart, 256, 256, pw1, 256, 255, nullptr, nullptr, pre, 256, 1);
    // gih = pre1 @ wih^T + bih + bhh
    k_gemm<<<dim3(32, 8), 256>>>(pre, 256, 256, wih, 256, 2047, bih, bhh, gih, 2048, 0);
    // base = inputs @ ow0[:, :512]^T + ob0
    k_gemm<<<dim3(16, 1), 256>>>(inputs, 512, 512, ow0, 1024, 255, ob0, nullptr, base, 256, 0);
    // LSTM scan
    k_scan<<<64, 256, SCAN_SMEM>>>(whh);
    // hpart = hall @ ow0[:, 512:]^T
    k_gemm<<<dim3(32, 1), 256>>>(hall, 512, 512, ow0 + 512, 1024, 255, nullptr, nullptr, hpart, 256, 0);
    // fused obs-net + emission
    k_big<<<4096, 256, BIG_SMEM>>>(mels, ow1, ob1, ow2, ob2, inputs_len);
    // HMM forward
    k_hmm<<<8, 128>>>(inputs_len, mel_lens, out);
}